// round 1
// baseline (speedup 1.0000x reference)
#include <cuda_runtime.h>

#define NS 4096

// ---- scratch (device globals: no allocation allowed) ----
__device__ float g_P[512 * 256];     // prefix table  (c0,c1,c2)
__device__ float g_S[512 * 256];     // suffix table  (c5,c6,c7)
__device__ float g_V1[NS * 256];     // intermediate after level-3 GEMM
__device__ int   g_p[NS];            // prefix index per sample
__device__ int   g_q[NS];            // suffix index per sample
__device__ int   g_cnt3[8];
__device__ int   g_cnt4[8];
__device__ int   g_b3[8 * NS];       // bucket sample ids per level-3 digit
__device__ int   g_b4[8 * NS];       // bucket sample ids per level-4 digit

// ---------------------------------------------------------------------------
__global__ void k_zero() {
    if (threadIdx.x < 8) { g_cnt3[threadIdx.x] = 0; g_cnt4[threadIdx.x] = 0; }
}

// Decode coords -> digits, prefix/suffix indices, digit buckets for levels 3/4.
__global__ void k_decode(const int* __restrict__ coords) {
    int n = blockIdx.x * blockDim.x + threadIdx.x;
    if (n >= NS) return;
    int x = coords[3 * n], y = coords[3 * n + 1], z = coords[3 * n + 2];
    int d[8];
#pragma unroll
    for (int l = 0; l < 8; l++) {
        int sh = 7 - l;
        d[l] = 4 * ((x >> sh) & 1) + 2 * ((y >> sh) & 1) + ((z >> sh) & 1);
    }
    g_p[n] = d[0] * 64 + d[1] * 8 + d[2];
    g_q[n] = d[5] * 64 + d[6] * 8 + d[7];
    int pos3 = atomicAdd(&g_cnt3[d[3]], 1);
    g_b3[d[3] * NS + pos3] = n;
    int pos4 = atomicAdd(&g_cnt4[d[4]], 1);
    g_b4[d[4] * NS + pos4] = n;
}

// Prefix table: P[p] = core0[0,c0,:] @ core1[:,c1,:] @ core2[:,c2,:]
// core0: [1,8,8]  core1: [8,8,64]  core2: [64,8,256]
__global__ void k_prefix(const float* __restrict__ c0,
                         const float* __restrict__ c1,
                         const float* __restrict__ c2) {
    int pidx = blockIdx.x;
    int a = pidx >> 6, b = (pidx >> 3) & 7, c = pidx & 7;
    __shared__ float t[64];
    int tid = threadIdx.x;
    if (tid < 64) {
        float acc = 0.f;
#pragma unroll
        for (int i = 0; i < 8; i++)
            acc += c0[a * 8 + i] * c1[(i * 8 + b) * 64 + tid];
        t[tid] = acc;
    }
    __syncthreads();
    float acc = 0.f;
#pragma unroll 8
    for (int r = 0; r < 64; r++)
        acc += t[r] * c2[(r * 8 + c) * 256 + tid];
    g_P[pidx * 256 + tid] = acc;
}

// Suffix table: S[q] = core5[:,c5,:] @ (core6[:,c6,:] @ core7[:,c7,0])
// core5: [256,8,64]  core6: [64,8,8]  core7: [8,8,1]
__global__ void k_suffix(const float* __restrict__ c5,
                         const float* __restrict__ c6,
                         const float* __restrict__ c7) {
    int qidx = blockIdx.x;
    int a = qidx >> 6, b = (qidx >> 3) & 7, c = qidx & 7;  // c5,c6,c7 digits
    __shared__ float u[64];
    int tid = threadIdx.x;
    if (tid < 64) {
        float acc = 0.f;
#pragma unroll
        for (int i = 0; i < 8; i++)
            acc += c6[(tid * 8 + b) * 8 + i] * c7[i * 8 + c];
        u[tid] = acc;
    }
    __syncthreads();
    float acc = 0.f;
#pragma unroll 8
    for (int j = 0; j < 64; j++)
        acc += c5[(tid * 8 + a) * 64 + j] * u[j];
    g_S[qidx * 256 + tid] = acc;
}

// ---------------------------------------------------------------------------
// Level-3 GEMM: for samples in bucket c, V1[n,:] = P[p[n],:] @ core3[:,c,:]
// core3 element (k, c, s) at k*2048 + c*256 + s.
// Tile: 32 samples x 256 cols, K=256. 256 threads: tid&63 -> col/4, tid>>6 -> 8-sample group.
__global__ void k_gemm3(const float* __restrict__ B) {
    int c = blockIdx.y;
    int cnt = g_cnt3[c];
    int base = blockIdx.x * 32;
    if (base >= cnt) return;

    __shared__ float As[32][260];
    __shared__ int   sn[32];
    __shared__ int   sp[32];
    int tid = threadIdx.x;
    if (tid < 32) {
        int li = base + tid;
        int n = (li < cnt) ? g_b3[c * NS + li] : -1;
        sn[tid] = n;
        sp[tid] = (n >= 0) ? g_p[n] : 0;
    }
    __syncthreads();
    for (int idx = tid; idx < 32 * 64; idx += 256) {
        int row = idx >> 6, kc = idx & 63;
        float4 v = make_float4(0.f, 0.f, 0.f, 0.f);
        if (sn[row] >= 0)
            v = *(const float4*)(g_P + sp[row] * 256 + kc * 4);
        *(float4*)&As[row][kc * 4] = v;
    }
    __syncthreads();

    int colg = tid & 63;
    int sg = tid >> 6;
    const float* Bp = B + c * 256 + colg * 4;
    float acc[8][4];
#pragma unroll
    for (int i = 0; i < 8; i++) { acc[i][0] = 0.f; acc[i][1] = 0.f; acc[i][2] = 0.f; acc[i][3] = 0.f; }

    for (int k = 0; k < 256; k += 4) {
        float4 b0 = __ldg((const float4*)(Bp + (k + 0) * 2048));
        float4 b1 = __ldg((const float4*)(Bp + (k + 1) * 2048));
        float4 b2 = __ldg((const float4*)(Bp + (k + 2) * 2048));
        float4 b3 = __ldg((const float4*)(Bp + (k + 3) * 2048));
#pragma unroll
        for (int i = 0; i < 8; i++) {
            float4 a = *(const float4*)&As[sg * 8 + i][k];
            acc[i][0] += a.x * b0.x; acc[i][1] += a.x * b0.y; acc[i][2] += a.x * b0.z; acc[i][3] += a.x * b0.w;
            acc[i][0] += a.y * b1.x; acc[i][1] += a.y * b1.y; acc[i][2] += a.y * b1.z; acc[i][3] += a.y * b1.w;
            acc[i][0] += a.z * b2.x; acc[i][1] += a.z * b2.y; acc[i][2] += a.z * b2.z; acc[i][3] += a.z * b2.w;
            acc[i][0] += a.w * b3.x; acc[i][1] += a.w * b3.y; acc[i][2] += a.w * b3.z; acc[i][3] += a.w * b3.w;
        }
    }
#pragma unroll
    for (int i = 0; i < 8; i++) {
        int n = sn[sg * 8 + i];
        if (n >= 0) {
            float4 o = make_float4(acc[i][0], acc[i][1], acc[i][2], acc[i][3]);
            *(float4*)(g_V1 + n * 256 + colg * 4) = o;
        }
    }
}

// ---------------------------------------------------------------------------
// Level-4 GEMM + suffix dot: out[n] = (V1[n,:] @ core4[:,c,:]) . S[q[n],:]
__global__ void k_gemm4(const float* __restrict__ B, float* __restrict__ out) {
    int c = blockIdx.y;
    int cnt = g_cnt4[c];
    int base = blockIdx.x * 32;
    if (base >= cnt) return;

    __shared__ float As[32][260];
    __shared__ int   sn[32];
    __shared__ float wsum[8][8];
    int tid = threadIdx.x;
    if (tid < 32) {
        int li = base + tid;
        sn[tid] = (li < cnt) ? g_b4[c * NS + li] : -1;
    }
    __syncthreads();
    for (int idx = tid; idx < 32 * 64; idx += 256) {
        int row = idx >> 6, kc = idx & 63;
        int n = sn[row];
        float4 v = make_float4(0.f, 0.f, 0.f, 0.f);
        if (n >= 0)
            v = *(const float4*)(g_V1 + n * 256 + kc * 4);
        *(float4*)&As[row][kc * 4] = v;
    }
    __syncthreads();

    int colg = tid & 63;
    int sg = tid >> 6;
    const float* Bp = B + c * 256 + colg * 4;
    float acc[8][4];
#pragma unroll
    for (int i = 0; i < 8; i++) { acc[i][0] = 0.f; acc[i][1] = 0.f; acc[i][2] = 0.f; acc[i][3] = 0.f; }

    for (int k = 0; k < 256; k += 4) {
        float4 b0 = __ldg((const float4*)(Bp + (k + 0) * 2048));
        float4 b1 = __ldg((const float4*)(Bp + (k + 1) * 2048));
        float4 b2 = __ldg((const float4*)(Bp + (k + 2) * 2048));
        float4 b3 = __ldg((const float4*)(Bp + (k + 3) * 2048));
#pragma unroll
        for (int i = 0; i < 8; i++) {
            float4 a = *(const float4*)&As[sg * 8 + i][k];
            acc[i][0] += a.x * b0.x; acc[i][1] += a.x * b0.y; acc[i][2] += a.x * b0.z; acc[i][3] += a.x * b0.w;
            acc[i][0] += a.y * b1.x; acc[i][1] += a.y * b1.y; acc[i][2] += a.y * b1.z; acc[i][3] += a.y * b1.w;
            acc[i][0] += a.z * b2.x; acc[i][1] += a.z * b2.y; acc[i][2] += a.z * b2.z; acc[i][3] += a.z * b2.w;
            acc[i][0] += a.w * b3.x; acc[i][1] += a.w * b3.y; acc[i][2] += a.w * b3.z; acc[i][3] += a.w * b3.w;
        }
    }

    // dot each sample row with its suffix vector; deterministic reduction
    float part[8];
#pragma unroll
    for (int i = 0; i < 8; i++) {
        int n = sn[sg * 8 + i];
        int q = (n >= 0) ? g_q[n] : 0;
        float4 s4 = *(const float4*)(g_S + q * 256 + colg * 4);
        part[i] = acc[i][0] * s4.x + acc[i][1] * s4.y + acc[i][2] * s4.z + acc[i][3] * s4.w;
    }
#pragma unroll
    for (int i = 0; i < 8; i++) {
#pragma unroll
        for (int off = 16; off > 0; off >>= 1)
            part[i] += __shfl_xor_sync(0xffffffffu, part[i], off);
    }
    int warp = tid >> 5, lane = tid & 31;
    if (lane == 0) {
#pragma unroll
        for (int i = 0; i < 8; i++) wsum[warp][i] = part[i];
    }
    __syncthreads();
    if (tid < 32) {
        int sg2 = tid >> 3, i = tid & 7;
        int n = sn[sg2 * 8 + i];
        if (n >= 0) out[n] = wsum[2 * sg2][i] + wsum[2 * sg2 + 1][i];
    }
}

// ---------------------------------------------------------------------------
extern "C" void kernel_launch(void* const* d_in, const int* in_sizes, int n_in,
                              void* d_out, int out_size) {
    const float* core0 = (const float*)d_in[0];
    const float* core1 = (const float*)d_in[1];
    const float* core2 = (const float*)d_in[2];
    const float* core3 = (const float*)d_in[3];
    const float* core4 = (const float*)d_in[4];
    const float* core5 = (const float*)d_in[5];
    const float* core6 = (const float*)d_in[6];
    const float* core7 = (const float*)d_in[7];
    const int*   coords = (const int*)d_in[8];
    float* out = (float*)d_out;

    k_zero<<<1, 32>>>();
    k_decode<<<(NS + 255) / 256, 256>>>(coords);
    k_prefix<<<512, 256>>>(core0, core1, core2);
    k_suffix<<<512, 256>>>(core5, core6, core7);
    k_gemm3<<<dim3(128, 8), 256>>>(core3);
    k_gemm4<<<dim3(128, 8), 256>>>(core4, out);
}